// round 12
// baseline (speedup 1.0000x reference)
#include <cuda_runtime.h>
#include <cuda_bf16.h>
#include <math.h>
#include <stdint.h>

// ----------------------------------------------------------------------------
// Shapes (fixed)
// ----------------------------------------------------------------------------
#define B 4
#define L 2048
#define H 8
#define E 64
#define C 512
#define L2 4096
#define TOPK 7
#define NTILE 32
#define NPAIR 528
#define NCAND 16
#define NRSB 64            // rescreen col-blocks (64 cols each)

// ----------------------------------------------------------------------------
// Device scratch
// ----------------------------------------------------------------------------
__device__ __nv_bfloat16 g_Zbf[(size_t)B * L2 * C];   // 16 MB bf16 Z = concat(q,k)
__device__ float g_Mpart[B * NTILE * L2];
__device__ float g_Spart[B * NTILE * L2];
__device__ float g_instAvg[B * L];
__device__ float g_d[B * L];
__device__ float g_corrPart[B * L];
__device__ int   g_cand[NCAND];
__device__ float g_cM[B * 2 * NCAND * NRSB];
__device__ float g_cS[B * 2 * NCAND * NRSB];
__device__ float g_csum[B * H * 32 * E];

// ----------------------------------------------------------------------------
// Helpers
// ----------------------------------------------------------------------------
#define SWZ(o) ((o) ^ (((o) >> 3) & 0x70))

__device__ __forceinline__ uint32_t smem_u32(const void* p) {
    uint32_t a;
    asm("{ .reg .u64 t; cvta.to.shared.u64 t, %1; cvt.u32.u64 %0, t; }"
        : "=r"(a) : "l"(p));
    return a;
}

#define LDSM4(r0, r1, r2, r3, addr)                                             \
    asm volatile("ldmatrix.sync.aligned.m8n8.x4.shared.b16 {%0,%1,%2,%3}, [%4];" \
                 : "=r"(r0), "=r"(r1), "=r"(r2), "=r"(r3) : "r"(addr))

#define MMA16816(c, a, b0v, b1v)                                                \
    asm volatile("mma.sync.aligned.m16n8k16.row.col.f32.bf16.bf16.f32 "         \
                 "{%0,%1,%2,%3},{%4,%5,%6,%7},{%8,%9},{%0,%1,%2,%3};"           \
                 : "+f"((c)[0]), "+f"((c)[1]), "+f"((c)[2]), "+f"((c)[3])       \
                 : "r"((a)[0]), "r"((a)[1]), "r"((a)[2]), "r"((a)[3]),          \
                   "r"(b0v), "r"(b1v))

#define CPASYNC16(dst, src)                                                     \
    asm volatile("cp.async.cg.shared.global [%0], [%1], 16;"                    \
                 :: "r"(dst), "l"(src) : "memory")
#define CPCOMMIT() asm volatile("cp.async.commit_group;" ::: "memory")
#define CPWAIT(n)  asm volatile("cp.async.wait_group %0;" :: "n"(n) : "memory")

// upper-triangle index for 8x8 symmetric gram: i<=j
#define TRI(i, j) ((i) * (15 - (i)) / 2 + (j))

// ----------------------------------------------------------------------------
// Kernel 0: convert Q,K fp32 -> bf16 Z (rows: q then k, per batch)
// ----------------------------------------------------------------------------
__global__ __launch_bounds__(256) void convert_kernel(const float* __restrict__ Q,
                                                      const float* __restrict__ K) {
    long t = (long)blockIdx.x * 256 + threadIdx.x;
    long e = t * 8;
    int b = (int)(e / ((long)L2 * C));
    long r = e % ((long)L2 * C);
    int row = (int)(r / C);
    int k = (int)(r % C);
    const float* src = (row < L) ? Q + ((long)b * L + row) * C + k
                                 : K + ((long)b * L + (row - L)) * C + k;
    float4 f0 = *(const float4*)(src);
    float4 f1 = *(const float4*)(src + 4);
    __nv_bfloat162 h0 = __float22bfloat162_rn(make_float2(f0.x, f0.y));
    __nv_bfloat162 h1 = __float22bfloat162_rn(make_float2(f0.z, f0.w));
    __nv_bfloat162 h2 = __float22bfloat162_rn(make_float2(f1.x, f1.y));
    __nv_bfloat162 h3 = __float22bfloat162_rn(make_float2(f1.z, f1.w));
    uint4 o;
    o.x = *(uint32_t*)&h0; o.y = *(uint32_t*)&h1;
    o.z = *(uint32_t*)&h2; o.w = *(uint32_t*)&h3;
    *(uint4*)(g_Zbf + e) = o;
}

// ----------------------------------------------------------------------------
// Kernel 1: instance-CL, warp-per-t, register accumulators.
// ----------------------------------------------------------------------------
__global__ __launch_bounds__(128) void instance_kernel(const float* __restrict__ Q,
                                                       const float* __restrict__ K) {
    const int wid = threadIdx.x >> 5, ln = threadIdx.x & 31;
    const int t = blockIdx.x * 4 + wid;

    float acc[36];
    #pragma unroll
    for (int p = 0; p < 36; p++) acc[p] = 0.f;

    #pragma unroll 2
    for (int ck = 0; ck < 16; ck++) {
        const int c = ck * 32 + ln;
        float z[8];
        #pragma unroll
        for (int v = 0; v < 4; v++) z[v] = __ldg(Q + ((size_t)v * L + t) * C + c);
        #pragma unroll
        for (int v = 0; v < 4; v++) z[4 + v] = __ldg(K + ((size_t)v * L + t) * C + c);
        int p = 0;
        #pragma unroll
        for (int i = 0; i < 8; i++)
            #pragma unroll
            for (int j = i; j < 8; j++) { acc[p] = fmaf(z[i], z[j], acc[p]); p++; }
    }

    #pragma unroll
    for (int p = 0; p < 36; p++) {
        #pragma unroll
        for (int o = 16; o > 0; o >>= 1)
            acc[p] += __shfl_xor_sync(0xffffffffu, acc[p], o);
    }

    float lse[8];
    #pragma unroll
    for (int r = 0; r < 8; r++) {
        float m = -INFINITY;
        #pragma unroll
        for (int j = 0; j < 8; j++) {
            if (j == r) continue;
            float g = (j < r) ? acc[TRI(j, r)] : acc[TRI(r, j)];
            m = fmaxf(m, g);
        }
        float s = 0.f;
        #pragma unroll
        for (int j = 0; j < 8; j++) {
            if (j == r) continue;
            float g = (j < r) ? acc[TRI(j, r)] : acc[TRI(r, j)];
            s += __expf(g - m);
        }
        lse[r] = m + logf(s);
    }

    if (ln < 4) {
        g_instAvg[ln * L + t] = 0.5f * (lse[ln] + lse[ln + 4]);
        g_d[ln * L + t] = acc[TRI(ln, ln + 4)];
    }
}

// ----------------------------------------------------------------------------
// Kernel 2: symmetric temporal gram, mma.sync bf16, 64x32 warp tile,
// 2-stage cp.async pipeline, SINGLE barrier per chunk (cp.async for ck+1 is
// issued after the top sync, so the old bottom sync is provably redundant).
// ----------------------------------------------------------------------------
__global__ __launch_bounds__(256, 2) void temporal_mma() {
    int p = blockIdx.x;
    int i = 0;
    while (p >= NTILE - i) { p -= NTILE - i; i++; }
    const int j = i + p;
    const int b = blockIdx.y;

    extern __shared__ __align__(1024) char dsm[];
    const uint32_t aBase = smem_u32(dsm);            // As[2]: 32 KB
    const uint32_t bBase = aBase + 32768;            // Bs[2]: 32 KB
    float* rmW = (float*)dsm;                        // reuse post-mainloop
    float* smW = rmW + 512;                          // [4][128]
    float* cmW = smW + 512;                          // [2][128]
    float* csW = cmW + 256;                          // [2][128]

    const int tid = threadIdx.x;
    const int ln = tid & 31;
    const int wr = (tid >> 5) >> 2;                  // 0..1 (64-row half)
    const int wc = (tid >> 5) & 3;                   // 0..3 (32-col quadrant)
    const int qr = ln >> 2, qc = ln & 3;

    const __nv_bfloat16* Zb = g_Zbf + (size_t)b * L2 * C;
    const __nv_bfloat16* Arows = Zb + (size_t)i * 128 * C;
    const __nv_bfloat16* Brows = Zb + (size_t)j * 128 * C;

    const int ldSeg = tid & 7;
    const int ldRow[4] = {(tid + 0) >> 3, (tid + 256) >> 3,
                          (tid + 512) >> 3, (tid + 768) >> 3};
    const uint32_t ldOff[4] = {
        (uint32_t)SWZ(ldRow[0] * 128 + ldSeg * 16),
        (uint32_t)SWZ(ldRow[1] * 128 + ldSeg * 16),
        (uint32_t)SWZ(ldRow[2] * 128 + ldSeg * 16),
        (uint32_t)SWZ(ldRow[3] * 128 + ldSeg * 16)};

    const int blk = ln >> 3, r8 = ln & 7;

    const int rowA0 = wr * 64 + (blk & 1) * 8 + r8;
    const int maskA = (rowA0 * 16) & 0x70;
    const uint32_t pA = (uint32_t)(maskA >> 5);
    const uint32_t cA0 = rowA0 * 128 + ((((blk >> 1) << 4)) ^ (maskA & 0x10));

    const int rowB0 = wc * 32 + (blk >> 1) * 8 + r8;
    const int maskB = (rowB0 * 16) & 0x70;
    const uint32_t pB = (uint32_t)(maskB >> 5);
    const uint32_t cB0 = rowB0 * 128 + ((((blk & 1) << 4)) ^ (maskB & 0x10));

    float acc[4][4][4];            // [mt 16-row][nt 8-col][quad]
    #pragma unroll
    for (int mt = 0; mt < 4; mt++)
        #pragma unroll
        for (int nt = 0; nt < 4; nt++)
            #pragma unroll
            for (int q = 0; q < 4; q++) acc[mt][nt][q] = 0.f;

    // prologue: chunk 0
    {
        #pragma unroll
        for (int u = 0; u < 4; u++) {
            CPASYNC16(aBase + ldOff[u], Arows + (size_t)ldRow[u] * C + ldSeg * 8);
            CPASYNC16(bBase + ldOff[u], Brows + (size_t)ldRow[u] * C + ldSeg * 8);
        }
        CPCOMMIT();
    }

    #pragma unroll 1
    for (int ck = 0; ck < 8; ck++) {
        CPWAIT(0);
        __syncthreads();
        if (ck < 7) {
            const uint32_t abuf = aBase + ((ck + 1) & 1) * 16384;
            const uint32_t bbuf = bBase + ((ck + 1) & 1) * 16384;
            const int co = (ck + 1) * 64;
            #pragma unroll
            for (int u = 0; u < 4; u++) {
                CPASYNC16(abuf + ldOff[u], Arows + (size_t)ldRow[u] * C + co + ldSeg * 8);
                CPASYNC16(bbuf + ldOff[u], Brows + (size_t)ldRow[u] * C + co + ldSeg * 8);
            }
            CPCOMMIT();
        }

        const uint32_t abA = aBase + (ck & 1) * 16384;
        const uint32_t bbB = bBase + (ck & 1) * 16384;
        #pragma unroll
        for (uint32_t ks = 0; ks < 4; ks++) {
            const uint32_t offA = ((ks ^ pA) << 5);
            const uint32_t offB = ((ks ^ pB) << 5);
            uint32_t af[4][4];
            #pragma unroll
            for (int mt = 0; mt < 4; mt++)
                LDSM4(af[mt][0], af[mt][1], af[mt][2], af[mt][3],
                      abA + cA0 + mt * (16 * 128) + offA);
            #pragma unroll
            for (int nn = 0; nn < 2; nn++) {
                uint32_t bf0, bf1, bf2, bf3;
                LDSM4(bf0, bf1, bf2, bf3, bbB + cB0 + nn * (16 * 128) + offB);
                #pragma unroll
                for (int mt = 0; mt < 4; mt++) {
                    MMA16816(acc[mt][2 * nn], af[mt], bf0, bf1);
                    MMA16816(acc[mt][2 * nn + 1], af[mt], bf2, bf3);
                }
            }
        }
    }
    __syncthreads();   // mainloop smem reads done before epilogue reuse

    // diagonal exclusion (only diag tile)
    if (i == j) {
        #pragma unroll
        for (int mt = 0; mt < 4; mt++)
            #pragma unroll
            for (int nt = 0; nt < 4; nt++)
                #pragma unroll
                for (int h = 0; h < 2; h++)
                    #pragma unroll
                    for (int q = 0; q < 2; q++) {
                        int rI = wr * 64 + mt * 16 + h * 8 + qr;
                        int cI = wc * 32 + nt * 8 + qc * 2 + q;
                        if (rI == cI) acc[mt][nt][h * 2 + q] = -INFINITY;
                    }
    }

    // ---- row-side LSE partials (slot j): 4 col-quadrant partials ----
    #pragma unroll
    for (int mt = 0; mt < 4; mt++)
        #pragma unroll
        for (int h = 0; h < 2; h++) {
            float m = -INFINITY;
            #pragma unroll
            for (int nt = 0; nt < 4; nt++)
                m = fmaxf(m, fmaxf(acc[mt][nt][h * 2], acc[mt][nt][h * 2 + 1]));
            m = fmaxf(m, __shfl_xor_sync(0xffffffffu, m, 1));
            m = fmaxf(m, __shfl_xor_sync(0xffffffffu, m, 2));
            if (qc == 0) rmW[wc * 128 + wr * 64 + mt * 16 + h * 8 + qr] = m;
        }
    __syncthreads();
    #pragma unroll
    for (int mt = 0; mt < 4; mt++)
        #pragma unroll
        for (int h = 0; h < 2; h++) {
            int r = wr * 64 + mt * 16 + h * 8 + qr;
            float Mf = fmaxf(fmaxf(rmW[r], rmW[128 + r]),
                             fmaxf(rmW[256 + r], rmW[384 + r]));
            float thr = Mf - 17.0f;
            float s = 0.f;
            #pragma unroll
            for (int nt = 0; nt < 4; nt++)
                #pragma unroll
                for (int q = 0; q < 2; q++) {
                    float v = acc[mt][nt][h * 2 + q];
                    if (v > thr) s += __expf(v - Mf);
                }
            s += __shfl_xor_sync(0xffffffffu, s, 1);
            s += __shfl_xor_sync(0xffffffffu, s, 2);
            if (qc == 0) smW[wc * 128 + r] = s;
        }
    __syncthreads();
    if (tid < 128) {
        float Mf = fmaxf(fmaxf(rmW[tid], rmW[128 + tid]),
                         fmaxf(rmW[256 + tid], rmW[384 + tid]));
        float S = smW[tid] + smW[128 + tid] + smW[256 + tid] + smW[384 + tid];
        int gi = (b * NTILE + j) * L2 + i * 128 + tid;
        g_Mpart[gi] = Mf;
        g_Spart[gi] = S;
    }

    // ---- col-side LSE partials (slot i), only off-diagonal ----
    if (i != j) {
        #pragma unroll
        for (int nt = 0; nt < 4; nt++)
            #pragma unroll
            for (int q = 0; q < 2; q++) {
                float m = -INFINITY;
                #pragma unroll
                for (int mt = 0; mt < 4; mt++)
                    #pragma unroll
                    for (int h = 0; h < 2; h++)
                        m = fmaxf(m, acc[mt][nt][h * 2 + q]);
                m = fmaxf(m, __shfl_xor_sync(0xffffffffu, m, 4));
                m = fmaxf(m, __shfl_xor_sync(0xffffffffu, m, 8));
                m = fmaxf(m, __shfl_xor_sync(0xffffffffu, m, 16));
                if (qr == 0) cmW[wr * 128 + wc * 32 + nt * 8 + qc * 2 + q] = m;
            }
        __syncthreads();
        #pragma unroll
        for (int nt = 0; nt < 4; nt++)
            #pragma unroll
            for (int q = 0; q < 2; q++) {
                int cI = wc * 32 + nt * 8 + qc * 2 + q;
                float Mf = fmaxf(cmW[cI], cmW[128 + cI]);
                float thr = Mf - 17.0f;
                float s = 0.f;
                #pragma unroll
                for (int mt = 0; mt < 4; mt++)
                    #pragma unroll
                    for (int h = 0; h < 2; h++) {
                        float v = acc[mt][nt][h * 2 + q];
                        if (v > thr) s += __expf(v - Mf);
                    }
                s += __shfl_xor_sync(0xffffffffu, s, 4);
                s += __shfl_xor_sync(0xffffffffu, s, 8);
                s += __shfl_xor_sync(0xffffffffu, s, 16);
                if (qr == 0) csW[wr * 128 + cI] = s;
            }
        __syncthreads();
        if (tid < 128) {
            float Mf = fmaxf(cmW[tid], cmW[128 + tid]);
            float S = csW[tid] + csW[128 + tid];
            int gi = (b * NTILE + i) * L2 + j * 128 + tid;
            g_Mpart[gi] = Mf;
            g_Spart[gi] = S;
        }
    }
}

// ----------------------------------------------------------------------------
// Kernel 3: combine 32 partials per row -> corrPart[b][t].
// ----------------------------------------------------------------------------
__global__ __launch_bounds__(256) void combine_kernel() {
    const int tl = threadIdx.x & 63;
    const int g = threadIdx.x >> 6;                  // 0..3
    const int t = blockIdx.x * 64 + tl;
    const int b = blockIdx.y;

    __shared__ float sM[2][4][64], sS[2][4][64];

    #pragma unroll
    for (int hh = 0; hh < 2; hh++) {
        const int row = t + hh * L;
        float M = -INFINITY;
        #pragma unroll
        for (int u = 0; u < 8; u++)
            M = fmaxf(M, g_Mpart[(b * NTILE + g * 8 + u) * L2 + row]);
        float S = 0.f;
        #pragma unroll
        for (int u = 0; u < 8; u++)
            S += g_Spart[(b * NTILE + g * 8 + u) * L2 + row] *
                 __expf(g_Mpart[(b * NTILE + g * 8 + u) * L2 + row] - M);
        sM[hh][g][tl] = M;
        sS[hh][g][tl] = S;
    }
    __syncthreads();

    if (g == 0) {
        float lse[2];
        #pragma unroll
        for (int hh = 0; hh < 2; hh++) {
            float M = fmaxf(fmaxf(sM[hh][0][tl], sM[hh][1][tl]),
                            fmaxf(sM[hh][2][tl], sM[hh][3][tl]));
            float S = 0.f;
            #pragma unroll
            for (int u = 0; u < 4; u++)
                S += sS[hh][u][tl] * __expf(sM[hh][u][tl] - M);
            lse[hh] = M + logf(S);
        }
        const float tAvg = 0.5f * (lse[0] + lse[1]);
        g_corrPart[b * L + t] =
            0.5f * g_instAvg[b * L + t] + 0.5f * tAvg - g_d[b * L + t];
    }
}

// ----------------------------------------------------------------------------
// Kernel 4: top-NCAND candidate extraction (single warp).
// ----------------------------------------------------------------------------
__global__ __launch_bounds__(32) void cand_kernel() {
    const int ln = threadIdx.x;
    float v[64];
    #pragma unroll
    for (int u = 0; u < 64; u++) {
        int idx = u * 32 + ln;
        v[u] = g_corrPart[idx] + g_corrPart[L + idx] +
               g_corrPart[2 * L + idx] + g_corrPart[3 * L + idx];
    }
    float pv = INFINITY;
    int pi = -1;
    for (int r = 0; r < NCAND; r++) {
        float bv = -INFINITY;
        int bi = 1 << 30;
        #pragma unroll
        for (int u = 0; u < 64; u++) {
            int idx = u * 32 + ln;
            bool lt = (v[u] < pv) || (v[u] == pv && idx > pi);
            if (lt && (v[u] > bv || (v[u] == bv && idx < bi))) { bv = v[u]; bi = idx; }
        }
        #pragma unroll
        for (int o = 16; o > 0; o >>= 1) {
            float ov = __shfl_xor_sync(0xffffffffu, bv, o);
            int oi = __shfl_xor_sync(0xffffffffu, bi, o);
            if (ov > bv || (ov == bv && oi < bi)) { bv = ov; bi = oi; }
        }
        if (ln == 0) g_cand[r] = bi;
        pv = bv; pi = bi;
    }
}

// ----------------------------------------------------------------------------
// Kernel 5: exact fp32 rescreen of NCAND candidates. Grid (NRSB=64, B).
// ----------------------------------------------------------------------------
__global__ __launch_bounds__(256) void rescreen(const float* __restrict__ Q,
                                                const float* __restrict__ K) {
    const int blk = blockIdx.x, b = blockIdx.y;
    __shared__ float czT[32][32];
    __shared__ float colT[32][64];
    __shared__ float pr[16][32];
    __shared__ float Mrow[32];
    __shared__ int cand[NCAND];

    const int tid = threadIdx.x;
    const int tcg = tid >> 4, tcol = tid & 15;
    if (tid < NCAND) cand[tid] = g_cand[tid];
    __syncthreads();

    float sc[2][4];
    #pragma unroll
    for (int cc = 0; cc < 2; cc++)
        #pragma unroll
        for (int w = 0; w < 4; w++) sc[cc][w] = 0.f;

    for (int ck = 0; ck < 16; ck++) {
        __syncthreads();
        for (int idx = tid; idx < 32 * 32; idx += 256) {
            int r = idx >> 5, kk = idx & 31;
            int c = r >> 1, h = r & 1;
            int t = cand[c];
            const float* src = h ? (K + ((size_t)b * L + t) * C)
                                 : (Q + ((size_t)b * L + t) * C);
            czT[kk][r] = src[ck * 32 + kk];
        }
        for (int idx = tid; idx < 64 * 32; idx += 256) {
            int r = idx >> 5, kk = idx & 31;
            int gid = blk * 64 + r;
            const float* src = (gid < L) ? (Q + ((size_t)b * L + gid) * C)
                                         : (K + ((size_t)b * L + gid - L) * C);
            colT[kk][r] = src[ck * 32 + kk];
        }
        __syncthreads();
        #pragma unroll 4
        for (int kk = 0; kk < 32; kk++) {
            float a0 = czT[kk][tcg], a1 = czT[kk][tcg + 16];
            float bv[4];
            #pragma unroll
            for (int w = 0; w < 4; w++) bv[w] = colT[kk][tcol + 16 * w];
            #pragma unroll
            for (int w = 0; w < 4; w++) {
                sc[0][w] = fmaf(a0, bv[w], sc[0][w]);
                sc[1][w] = fmaf(a1, bv[w], sc[1][w]);
            }
        }
    }

    #pragma unroll
    for (int cc = 0; cc < 2; cc++) {
        int ci = tcg + 16 * cc;
        int rowid = cand[ci >> 1] + (ci & 1) * L;
        #pragma unroll
        for (int w = 0; w < 4; w++) {
            int gid = blk * 64 + tcol + 16 * w;
            if (gid == rowid) sc[cc][w] = -INFINITY;
        }
    }

    __syncthreads();
    #pragma unroll
    for (int cc = 0; cc < 2; cc++) {
        int ci = tcg + 16 * cc;
        float m = sc[cc][0];
        #pragma unroll
        for (int w = 1; w < 4; w++) m = fmaxf(m, sc[cc][w]);
        pr[tcol][ci] = m;
    }
    __syncthreads();
    if (tid < 32) {
        float m = pr[0][tid];
        #pragma unroll
        for (int x = 1; x < 16; x++) m = fmaxf(m, pr[x][tid]);
        Mrow[tid] = m;
    }
    __syncthreads();
    #pragma unroll
    for (int cc = 0; cc < 2; cc++) {
        int ci = tcg + 16 * cc;
        float Mf = Mrow[ci];
        float s = 0.f;
        #pragma unroll
        for (int w = 0; w < 4; w++) s += __expf(sc[cc][w] - Mf);
        pr[tcol][ci] = s;
    }
    __syncthreads();
    if (tid < 32) {
        float s = 0.f;
        #pragma unroll
        for (int x = 0; x < 16; x++) s += pr[x][tid];
        int gi = (b * 32 + tid) * NRSB + blk;
        g_cM[gi] = Mrow[tid];
        g_cS[gi] = s;
    }
}

// ----------------------------------------------------------------------------
// Kernel 6: final exact top-7 among candidates + in-place fixup of the 7
// selected rows of the (already written) plain cumsum output.
// ----------------------------------------------------------------------------
__global__ __launch_bounds__(256) void final_topk_fixup(float* __restrict__ out) {
    __shared__ float ls[B][32];
    __shared__ float val[NCAND];
    __shared__ int topk[TOPK];
    const int tid = threadIdx.x;

    if (tid < 32) {
        for (int b = 0; b < B; b++) {
            float M = -INFINITY;
            #pragma unroll
            for (int blk = 0; blk < NRSB; blk++)
                M = fmaxf(M, g_cM[(b * 32 + tid) * NRSB + blk]);
            float S = 0.f;
            #pragma unroll
            for (int blk = 0; blk < NRSB; blk++)
                S += g_cS[(b * 32 + tid) * NRSB + blk] *
                     __expf(g_cM[(b * 32 + tid) * NRSB + blk] - M);
            ls[b][tid] = M + logf(S);
        }
    }
    __syncthreads();
    if (tid < NCAND) {
        int t = g_cand[tid];
        float sum = 0.f;
        for (int b = 0; b < B; b++) {
            float tavg = 0.5f * (ls[b][2 * tid] + ls[b][2 * tid + 1]);
            sum += 0.5f * g_instAvg[b * L + t] + 0.5f * tavg - g_d[b * L + t];
        }
        val[tid] = sum * 0.25f;
    }
    __syncthreads();
    if (tid == 0) {
        unsigned used = 0;
        for (int k = 0; k < TOPK; k++) {
            float best = -INFINITY;
            int bc = -1, bt = 1 << 30;
            for (int c = 0; c < NCAND; c++) {
                if ((used >> c) & 1) continue;
                int t = g_cand[c];
                if (val[c] > best || (val[c] == best && t < bt)) {
                    best = val[c]; bc = c; bt = t;
                }
            }
            used |= 1u << bc;
            topk[k] = g_cand[bc];
        }
    }
    __syncthreads();

    // fixup: 32 bh x TOPK x 64 e = 14336 elements
    for (int idx = tid; idx < B * H * TOPK * E; idx += 256) {
        const int e = idx & 63;
        const int k = (idx >> 6) % TOPK;
        const int bh = idx / (64 * TOPK);
        const int r = topk[k];
        const size_t o = ((size_t)bh * L + r) * E + e;
        out[o] = out[o] / (float)(r + 1);
    }
}

// ----------------------------------------------------------------------------
// Kernel 7a: chunk sums for cumsum. Grid (32 chunks, H, B), 64 threads.
// ----------------------------------------------------------------------------
__global__ __launch_bounds__(64) void cumsum_pass1(const float* __restrict__ V) {
    const int chunk = blockIdx.x, h = blockIdx.y, b = blockIdx.z;
    const int e = threadIdx.x;
    const long baseIn = (long)b * L * C + (long)h * E + e;
    const int l0 = chunk * 64;
    float s = 0.f;
    #pragma unroll 8
    for (int i = 0; i < 64; i++) s += V[baseIn + (long)(l0 + i) * C];
    g_csum[((b * H + h) * 32 + chunk) * E + e] = s;
}

// ----------------------------------------------------------------------------
// Kernel 7b: PLAIN scan (no rescale) -> out, on the side stream.
// ----------------------------------------------------------------------------
__global__ __launch_bounds__(64) void cumsum_pass2_plain(const float* __restrict__ V,
                                                         float* __restrict__ out) {
    const int chunk = blockIdx.x, h = blockIdx.y, b = blockIdx.z;
    const int e = threadIdx.x;

    float off = 0.f;
    for (int c = 0; c < chunk; c++)
        off += g_csum[((b * H + h) * 32 + c) * E + e];

    const long baseIn = (long)b * L * C + (long)h * E + e;
    const long baseOut = ((long)(b * H + h) * L) * E + e;
    const int l0 = chunk * 64;
    float acc = off;
    #pragma unroll 4
    for (int i = 0; i < 64; i++) {
        const int l = l0 + i;
        acc += V[baseIn + (long)l * C];
        out[baseOut + (long)l * E] = acc;
    }
}

// ----------------------------------------------------------------------------
// Launch. Order chosen so temporal_mma is the 4th kernel launch (ncu slot):
// instance(1,s1), pass1(2,s1), convert(3,main), temporal(4,main),
// pass2(5,s1), combine(6), cand(7), rescreen(8), final_topk_fixup(9).
// ----------------------------------------------------------------------------
extern "C" void kernel_launch(void* const* d_in, const int* in_sizes, int n_in,
                              void* d_out, int out_size) {
    const float* Q = (const float*)d_in[0];
    const float* K = (const float*)d_in[1];
    const float* V = (const float*)d_in[2];
    float* out = (float*)d_out;

    static cudaStream_t s1 = nullptr;
    static cudaEvent_t evFork = nullptr, evJoin = nullptr;
    static bool inited = false;
    if (!inited) {
        cudaFuncSetAttribute(temporal_mma,
                             cudaFuncAttributeMaxDynamicSharedMemorySize, 65536);
        cudaStreamCreateWithFlags(&s1, cudaStreamNonBlocking);
        cudaEventCreateWithFlags(&evFork, cudaEventDisableTiming);
        cudaEventCreateWithFlags(&evJoin, cudaEventDisableTiming);
        inited = true;
    }

    cudaEventRecord(evFork, 0);
    cudaStreamWaitEvent(s1, evFork, 0);

    // side stream (launches 1-2)
    instance_kernel<<<L / 4, 128, 0, s1>>>(Q, K);
    cumsum_pass1<<<dim3(32, H, B), 64, 0, s1>>>(V);

    // main stream (launches 3-4)
    convert_kernel<<<(B * L2 * C) / 8 / 256, 256>>>(Q, K);
    temporal_mma<<<dim3(NPAIR, B), 256, 65536>>>();

    // side stream (launch 5) + join
    cumsum_pass2_plain<<<dim3(32, H, B), 64, 0, s1>>>(V, out);
    cudaEventRecord(evJoin, s1);
    cudaStreamWaitEvent(0, evJoin, 0);   // instAvg/d for combine; out for fixup

    // main tail (launches 6-9)
    combine_kernel<<<dim3(L / 64, B), 256>>>();
    cand_kernel<<<1, 32>>>();
    rescreen<<<dim3(NRSB, B), 256>>>(Q, K);
    final_topk_fixup<<<1, 256>>>(out);
}

// round 13
// speedup vs baseline: 1.2065x; 1.2065x over previous
#include <cuda_runtime.h>
#include <cuda_bf16.h>
#include <math.h>
#include <stdint.h>

// ----------------------------------------------------------------------------
// Shapes (fixed)
// ----------------------------------------------------------------------------
#define B 4
#define L 2048
#define H 8
#define E 64
#define C 512
#define L2 4096
#define TOPK 7
#define NTILE 32
#define NPAIR 528
#define NCAND 16
#define NRSB 64            // rescreen col-blocks (64 cols each)

// ----------------------------------------------------------------------------
// Device scratch
// ----------------------------------------------------------------------------
__device__ __nv_bfloat16 g_Zbf[(size_t)B * L2 * C];   // 16 MB bf16 Z = concat(q,k)
__device__ float g_Mpart[B * NTILE * L2];
__device__ float g_Spart[B * NTILE * L2];
__device__ float g_instAvg[B * L];
__device__ float g_d[B * L];
__device__ float g_corrPart[B * L];
__device__ int   g_cand[NCAND];
__device__ float g_cM[B * 2 * NCAND * NRSB];
__device__ float g_cS[B * 2 * NCAND * NRSB];
__device__ int   g_topk[TOPK];
__device__ float g_csum[B * H * 32 * E];

// ----------------------------------------------------------------------------
// Helpers
// ----------------------------------------------------------------------------
#define SWZ(o) ((o) ^ (((o) >> 3) & 0x70))

__device__ __forceinline__ uint32_t smem_u32(const void* p) {
    uint32_t a;
    asm("{ .reg .u64 t; cvta.to.shared.u64 t, %1; cvt.u32.u64 %0, t; }"
        : "=r"(a) : "l"(p));
    return a;
}

#define LDSM4(r0, r1, r2, r3, addr)                                             \
    asm volatile("ldmatrix.sync.aligned.m8n8.x4.shared.b16 {%0,%1,%2,%3}, [%4];" \
                 : "=r"(r0), "=r"(r1), "=r"(r2), "=r"(r3) : "r"(addr))

#define MMA16816(c, a, b0v, b1v)                                                \
    asm volatile("mma.sync.aligned.m16n8k16.row.col.f32.bf16.bf16.f32 "         \
                 "{%0,%1,%2,%3},{%4,%5,%6,%7},{%8,%9},{%0,%1,%2,%3};"           \
                 : "+f"((c)[0]), "+f"((c)[1]), "+f"((c)[2]), "+f"((c)[3])       \
                 : "r"((a)[0]), "r"((a)[1]), "r"((a)[2]), "r"((a)[3]),          \
                   "r"(b0v), "r"(b1v))

#define CPASYNC16(dst, src)                                                     \
    asm volatile("cp.async.cg.shared.global [%0], [%1], 16;"                    \
                 :: "r"(dst), "l"(src) : "memory")
#define CPCOMMIT() asm volatile("cp.async.commit_group;" ::: "memory")
#define CPWAIT(n)  asm volatile("cp.async.wait_group %0;" :: "n"(n) : "memory")

// upper-triangle index for 8x8 symmetric gram: i<=j
#define TRI(i, j) ((i) * (15 - (i)) / 2 + (j))

// ----------------------------------------------------------------------------
// Kernel 0: convert Q,K fp32 -> bf16 Z (rows: q then k, per batch)
// ----------------------------------------------------------------------------
__global__ __launch_bounds__(256) void convert_kernel(const float* __restrict__ Q,
                                                      const float* __restrict__ K) {
    long t = (long)blockIdx.x * 256 + threadIdx.x;
    long e = t * 8;
    int b = (int)(e / ((long)L2 * C));
    long r = e % ((long)L2 * C);
    int row = (int)(r / C);
    int k = (int)(r % C);
    const float* src = (row < L) ? Q + ((long)b * L + row) * C + k
                                 : K + ((long)b * L + (row - L)) * C + k;
    float4 f0 = *(const float4*)(src);
    float4 f1 = *(const float4*)(src + 4);
    __nv_bfloat162 h0 = __float22bfloat162_rn(make_float2(f0.x, f0.y));
    __nv_bfloat162 h1 = __float22bfloat162_rn(make_float2(f0.z, f0.w));
    __nv_bfloat162 h2 = __float22bfloat162_rn(make_float2(f1.x, f1.y));
    __nv_bfloat162 h3 = __float22bfloat162_rn(make_float2(f1.z, f1.w));
    uint4 o;
    o.x = *(uint32_t*)&h0; o.y = *(uint32_t*)&h1;
    o.z = *(uint32_t*)&h2; o.w = *(uint32_t*)&h3;
    *(uint4*)(g_Zbf + e) = o;
}

// ----------------------------------------------------------------------------
// Kernel 1: instance-CL, warp-per-t, register accumulators.
// ----------------------------------------------------------------------------
__global__ __launch_bounds__(128) void instance_kernel(const float* __restrict__ Q,
                                                       const float* __restrict__ K) {
    const int wid = threadIdx.x >> 5, ln = threadIdx.x & 31;
    const int t = blockIdx.x * 4 + wid;

    float acc[36];
    #pragma unroll
    for (int p = 0; p < 36; p++) acc[p] = 0.f;

    #pragma unroll 2
    for (int ck = 0; ck < 16; ck++) {
        const int c = ck * 32 + ln;
        float z[8];
        #pragma unroll
        for (int v = 0; v < 4; v++) z[v] = __ldg(Q + ((size_t)v * L + t) * C + c);
        #pragma unroll
        for (int v = 0; v < 4; v++) z[4 + v] = __ldg(K + ((size_t)v * L + t) * C + c);
        int p = 0;
        #pragma unroll
        for (int i = 0; i < 8; i++)
            #pragma unroll
            for (int j = i; j < 8; j++) { acc[p] = fmaf(z[i], z[j], acc[p]); p++; }
    }

    #pragma unroll
    for (int p = 0; p < 36; p++) {
        #pragma unroll
        for (int o = 16; o > 0; o >>= 1)
            acc[p] += __shfl_xor_sync(0xffffffffu, acc[p], o);
    }

    float lse[8];
    #pragma unroll
    for (int r = 0; r < 8; r++) {
        float m = -INFINITY;
        #pragma unroll
        for (int j = 0; j < 8; j++) {
            if (j == r) continue;
            float g = (j < r) ? acc[TRI(j, r)] : acc[TRI(r, j)];
            m = fmaxf(m, g);
        }
        float s = 0.f;
        #pragma unroll
        for (int j = 0; j < 8; j++) {
            if (j == r) continue;
            float g = (j < r) ? acc[TRI(j, r)] : acc[TRI(r, j)];
            s += __expf(g - m);
        }
        lse[r] = m + logf(s);
    }

    if (ln < 4) {
        g_instAvg[ln * L + t] = 0.5f * (lse[ln] + lse[ln + 4]);
        g_d[ln * L + t] = acc[TRI(ln, ln + 4)];
    }
}

// ----------------------------------------------------------------------------
// Kernel 2: symmetric temporal gram, mma.sync bf16, 64x32 warp tile,
// 2-stage cp.async pipeline, single barrier per chunk (measured neutral).
// ----------------------------------------------------------------------------
__global__ __launch_bounds__(256, 2) void temporal_mma() {
    int p = blockIdx.x;
    int i = 0;
    while (p >= NTILE - i) { p -= NTILE - i; i++; }
    const int j = i + p;
    const int b = blockIdx.y;

    extern __shared__ __align__(1024) char dsm[];
    const uint32_t aBase = smem_u32(dsm);            // As[2]: 32 KB
    const uint32_t bBase = aBase + 32768;            // Bs[2]: 32 KB
    float* rmW = (float*)dsm;                        // reuse post-mainloop
    float* smW = rmW + 512;                          // [4][128]
    float* cmW = smW + 512;                          // [2][128]
    float* csW = cmW + 256;                          // [2][128]

    const int tid = threadIdx.x;
    const int ln = tid & 31;
    const int wr = (tid >> 5) >> 2;                  // 0..1 (64-row half)
    const int wc = (tid >> 5) & 3;                   // 0..3 (32-col quadrant)
    const int qr = ln >> 2, qc = ln & 3;

    const __nv_bfloat16* Zb = g_Zbf + (size_t)b * L2 * C;
    const __nv_bfloat16* Arows = Zb + (size_t)i * 128 * C;
    const __nv_bfloat16* Brows = Zb + (size_t)j * 128 * C;

    const int ldSeg = tid & 7;
    const int ldRow[4] = {(tid + 0) >> 3, (tid + 256) >> 3,
                          (tid + 512) >> 3, (tid + 768) >> 3};
    const uint32_t ldOff[4] = {
        (uint32_t)SWZ(ldRow[0] * 128 + ldSeg * 16),
        (uint32_t)SWZ(ldRow[1] * 128 + ldSeg * 16),
        (uint32_t)SWZ(ldRow[2] * 128 + ldSeg * 16),
        (uint32_t)SWZ(ldRow[3] * 128 + ldSeg * 16)};

    const int blk = ln >> 3, r8 = ln & 7;

    const int rowA0 = wr * 64 + (blk & 1) * 8 + r8;
    const int maskA = (rowA0 * 16) & 0x70;
    const uint32_t pA = (uint32_t)(maskA >> 5);
    const uint32_t cA0 = rowA0 * 128 + ((((blk >> 1) << 4)) ^ (maskA & 0x10));

    const int rowB0 = wc * 32 + (blk >> 1) * 8 + r8;
    const int maskB = (rowB0 * 16) & 0x70;
    const uint32_t pB = (uint32_t)(maskB >> 5);
    const uint32_t cB0 = rowB0 * 128 + ((((blk & 1) << 4)) ^ (maskB & 0x10));

    float acc[4][4][4];            // [mt 16-row][nt 8-col][quad]
    #pragma unroll
    for (int mt = 0; mt < 4; mt++)
        #pragma unroll
        for (int nt = 0; nt < 4; nt++)
            #pragma unroll
            for (int q = 0; q < 4; q++) acc[mt][nt][q] = 0.f;

    // prologue: chunk 0
    {
        #pragma unroll
        for (int u = 0; u < 4; u++) {
            CPASYNC16(aBase + ldOff[u], Arows + (size_t)ldRow[u] * C + ldSeg * 8);
            CPASYNC16(bBase + ldOff[u], Brows + (size_t)ldRow[u] * C + ldSeg * 8);
        }
        CPCOMMIT();
    }

    #pragma unroll 1
    for (int ck = 0; ck < 8; ck++) {
        CPWAIT(0);
        __syncthreads();
        if (ck < 7) {
            const uint32_t abuf = aBase + ((ck + 1) & 1) * 16384;
            const uint32_t bbuf = bBase + ((ck + 1) & 1) * 16384;
            const int co = (ck + 1) * 64;
            #pragma unroll
            for (int u = 0; u < 4; u++) {
                CPASYNC16(abuf + ldOff[u], Arows + (size_t)ldRow[u] * C + co + ldSeg * 8);
                CPASYNC16(bbuf + ldOff[u], Brows + (size_t)ldRow[u] * C + co + ldSeg * 8);
            }
            CPCOMMIT();
        }

        const uint32_t abA = aBase + (ck & 1) * 16384;
        const uint32_t bbB = bBase + (ck & 1) * 16384;
        #pragma unroll
        for (uint32_t ks = 0; ks < 4; ks++) {
            const uint32_t offA = ((ks ^ pA) << 5);
            const uint32_t offB = ((ks ^ pB) << 5);
            uint32_t af[4][4];
            #pragma unroll
            for (int mt = 0; mt < 4; mt++)
                LDSM4(af[mt][0], af[mt][1], af[mt][2], af[mt][3],
                      abA + cA0 + mt * (16 * 128) + offA);
            #pragma unroll
            for (int nn = 0; nn < 2; nn++) {
                uint32_t bf0, bf1, bf2, bf3;
                LDSM4(bf0, bf1, bf2, bf3, bbB + cB0 + nn * (16 * 128) + offB);
                #pragma unroll
                for (int mt = 0; mt < 4; mt++) {
                    MMA16816(acc[mt][2 * nn], af[mt], bf0, bf1);
                    MMA16816(acc[mt][2 * nn + 1], af[mt], bf2, bf3);
                }
            }
        }
    }
    __syncthreads();   // mainloop smem reads done before epilogue reuse

    // diagonal exclusion (only diag tile)
    if (i == j) {
        #pragma unroll
        for (int mt = 0; mt < 4; mt++)
            #pragma unroll
            for (int nt = 0; nt < 4; nt++)
                #pragma unroll
                for (int h = 0; h < 2; h++)
                    #pragma unroll
                    for (int q = 0; q < 2; q++) {
                        int rI = wr * 64 + mt * 16 + h * 8 + qr;
                        int cI = wc * 32 + nt * 8 + qc * 2 + q;
                        if (rI == cI) acc[mt][nt][h * 2 + q] = -INFINITY;
                    }
    }

    // ---- row-side LSE partials (slot j): 4 col-quadrant partials ----
    #pragma unroll
    for (int mt = 0; mt < 4; mt++)
        #pragma unroll
        for (int h = 0; h < 2; h++) {
            float m = -INFINITY;
            #pragma unroll
            for (int nt = 0; nt < 4; nt++)
                m = fmaxf(m, fmaxf(acc[mt][nt][h * 2], acc[mt][nt][h * 2 + 1]));
            m = fmaxf(m, __shfl_xor_sync(0xffffffffu, m, 1));
            m = fmaxf(m, __shfl_xor_sync(0xffffffffu, m, 2));
            if (qc == 0) rmW[wc * 128 + wr * 64 + mt * 16 + h * 8 + qr] = m;
        }
    __syncthreads();
    #pragma unroll
    for (int mt = 0; mt < 4; mt++)
        #pragma unroll
        for (int h = 0; h < 2; h++) {
            int r = wr * 64 + mt * 16 + h * 8 + qr;
            float Mf = fmaxf(fmaxf(rmW[r], rmW[128 + r]),
                             fmaxf(rmW[256 + r], rmW[384 + r]));
            float thr = Mf - 17.0f;
            float s = 0.f;
            #pragma unroll
            for (int nt = 0; nt < 4; nt++)
                #pragma unroll
                for (int q = 0; q < 2; q++) {
                    float v = acc[mt][nt][h * 2 + q];
                    if (v > thr) s += __expf(v - Mf);
                }
            s += __shfl_xor_sync(0xffffffffu, s, 1);
            s += __shfl_xor_sync(0xffffffffu, s, 2);
            if (qc == 0) smW[wc * 128 + r] = s;
        }
    __syncthreads();
    if (tid < 128) {
        float Mf = fmaxf(fmaxf(rmW[tid], rmW[128 + tid]),
                         fmaxf(rmW[256 + tid], rmW[384 + tid]));
        float S = smW[tid] + smW[128 + tid] + smW[256 + tid] + smW[384 + tid];
        int gi = (b * NTILE + j) * L2 + i * 128 + tid;
        g_Mpart[gi] = Mf;
        g_Spart[gi] = S;
    }

    // ---- col-side LSE partials (slot i), only off-diagonal ----
    if (i != j) {
        #pragma unroll
        for (int nt = 0; nt < 4; nt++)
            #pragma unroll
            for (int q = 0; q < 2; q++) {
                float m = -INFINITY;
                #pragma unroll
                for (int mt = 0; mt < 4; mt++)
                    #pragma unroll
                    for (int h = 0; h < 2; h++)
                        m = fmaxf(m, acc[mt][nt][h * 2 + q]);
                m = fmaxf(m, __shfl_xor_sync(0xffffffffu, m, 4));
                m = fmaxf(m, __shfl_xor_sync(0xffffffffu, m, 8));
                m = fmaxf(m, __shfl_xor_sync(0xffffffffu, m, 16));
                if (qr == 0) cmW[wr * 128 + wc * 32 + nt * 8 + qc * 2 + q] = m;
            }
        __syncthreads();
        #pragma unroll
        for (int nt = 0; nt < 4; nt++)
            #pragma unroll
            for (int q = 0; q < 2; q++) {
                int cI = wc * 32 + nt * 8 + qc * 2 + q;
                float Mf = fmaxf(cmW[cI], cmW[128 + cI]);
                float thr = Mf - 17.0f;
                float s = 0.f;
                #pragma unroll
                for (int mt = 0; mt < 4; mt++)
                    #pragma unroll
                    for (int h = 0; h < 2; h++) {
                        float v = acc[mt][nt][h * 2 + q];
                        if (v > thr) s += __expf(v - Mf);
                    }
                s += __shfl_xor_sync(0xffffffffu, s, 4);
                s += __shfl_xor_sync(0xffffffffu, s, 8);
                s += __shfl_xor_sync(0xffffffffu, s, 16);
                if (qr == 0) csW[wr * 128 + cI] = s;
            }
        __syncthreads();
        if (tid < 128) {
            float Mf = fmaxf(cmW[tid], cmW[128 + tid]);
            float S = csW[tid] + csW[128 + tid];
            int gi = (b * NTILE + i) * L2 + j * 128 + tid;
            g_Mpart[gi] = Mf;
            g_Spart[gi] = S;
        }
    }
}

// ----------------------------------------------------------------------------
// Kernel 3: combine 32 partials per row -> corrPart[b][t].
// ----------------------------------------------------------------------------
__global__ __launch_bounds__(256) void combine_kernel() {
    const int tl = threadIdx.x & 63;
    const int g = threadIdx.x >> 6;                  // 0..3
    const int t = blockIdx.x * 64 + tl;
    const int b = blockIdx.y;

    __shared__ float sM[2][4][64], sS[2][4][64];

    #pragma unroll
    for (int hh = 0; hh < 2; hh++) {
        const int row = t + hh * L;
        float M = -INFINITY;
        #pragma unroll
        for (int u = 0; u < 8; u++)
            M = fmaxf(M, g_Mpart[(b * NTILE + g * 8 + u) * L2 + row]);
        float S = 0.f;
        #pragma unroll
        for (int u = 0; u < 8; u++)
            S += g_Spart[(b * NTILE + g * 8 + u) * L2 + row] *
                 __expf(g_Mpart[(b * NTILE + g * 8 + u) * L2 + row] - M);
        sM[hh][g][tl] = M;
        sS[hh][g][tl] = S;
    }
    __syncthreads();

    if (g == 0) {
        float lse[2];
        #pragma unroll
        for (int hh = 0; hh < 2; hh++) {
            float M = fmaxf(fmaxf(sM[hh][0][tl], sM[hh][1][tl]),
                            fmaxf(sM[hh][2][tl], sM[hh][3][tl]));
            float S = 0.f;
            #pragma unroll
            for (int u = 0; u < 4; u++)
                S += sS[hh][u][tl] * __expf(sM[hh][u][tl] - M);
            lse[hh] = M + logf(S);
        }
        const float tAvg = 0.5f * (lse[0] + lse[1]);
        g_corrPart[b * L + t] =
            0.5f * g_instAvg[b * L + t] + 0.5f * tAvg - g_d[b * L + t];
    }
}

// ----------------------------------------------------------------------------
// Kernel 4: top-NCAND candidate extraction, 256 threads (8 values each).
// Lexicographic-next (val desc, idx asc) selection; two-level reduction.
// ----------------------------------------------------------------------------
__global__ __launch_bounds__(256) void cand_kernel() {
    const int tid = threadIdx.x;
    const int ln = tid & 31, wg = tid >> 5;
    __shared__ float swv[8];
    __shared__ int swi[8];
    __shared__ float sbv;
    __shared__ int sbi;

    float v[8];
    #pragma unroll
    for (int u = 0; u < 8; u++) {
        int idx = u * 256 + tid;
        v[u] = g_corrPart[idx] + g_corrPart[L + idx] +
               g_corrPart[2 * L + idx] + g_corrPart[3 * L + idx];
    }

    float pv = INFINITY;
    int pi = -1;
    for (int r = 0; r < NCAND; r++) {
        float bv = -INFINITY;
        int bi = 1 << 30;
        #pragma unroll
        for (int u = 0; u < 8; u++) {
            int idx = u * 256 + tid;
            bool lt = (v[u] < pv) || (v[u] == pv && idx > pi);
            if (lt && (v[u] > bv || (v[u] == bv && idx < bi))) { bv = v[u]; bi = idx; }
        }
        #pragma unroll
        for (int o = 16; o > 0; o >>= 1) {
            float ov = __shfl_xor_sync(0xffffffffu, bv, o);
            int oi = __shfl_xor_sync(0xffffffffu, bi, o);
            if (ov > bv || (ov == bv && oi < bi)) { bv = ov; bi = oi; }
        }
        if (ln == 0) { swv[wg] = bv; swi[wg] = bi; }
        __syncthreads();
        if (tid == 0) {
            float fb = swv[0]; int fi = swi[0];
            #pragma unroll
            for (int w = 1; w < 8; w++)
                if (swv[w] > fb || (swv[w] == fb && swi[w] < fi)) { fb = swv[w]; fi = swi[w]; }
            sbv = fb; sbi = fi;
            g_cand[r] = fi;
        }
        __syncthreads();
        pv = sbv; pi = sbi;
    }
}

// ----------------------------------------------------------------------------
// Kernel 5: exact fp32 rescreen of NCAND candidates. Grid (NRSB=64, B).
// ----------------------------------------------------------------------------
__global__ __launch_bounds__(256) void rescreen(const float* __restrict__ Q,
                                                const float* __restrict__ K) {
    const int blk = blockIdx.x, b = blockIdx.y;
    __shared__ float czT[32][32];
    __shared__ float colT[32][64];
    __shared__ float pr[16][32];
    __shared__ float Mrow[32];
    __shared__ int cand[NCAND];

    const int tid = threadIdx.x;
    const int tcg = tid >> 4, tcol = tid & 15;
    if (tid < NCAND) cand[tid] = g_cand[tid];
    __syncthreads();

    float sc[2][4];
    #pragma unroll
    for (int cc = 0; cc < 2; cc++)
        #pragma unroll
        for (int w = 0; w < 4; w++) sc[cc][w] = 0.f;

    for (int ck = 0; ck < 16; ck++) {
        __syncthreads();
        for (int idx = tid; idx < 32 * 32; idx += 256) {
            int r = idx >> 5, kk = idx & 31;
            int c = r >> 1, h = r & 1;
            int t = cand[c];
            const float* src = h ? (K + ((size_t)b * L + t) * C)
                                 : (Q + ((size_t)b * L + t) * C);
            czT[kk][r] = src[ck * 32 + kk];
        }
        for (int idx = tid; idx < 64 * 32; idx += 256) {
            int r = idx >> 5, kk = idx & 31;
            int gid = blk * 64 + r;
            const float* src = (gid < L) ? (Q + ((size_t)b * L + gid) * C)
                                         : (K + ((size_t)b * L + gid - L) * C);
            colT[kk][r] = src[ck * 32 + kk];
        }
        __syncthreads();
        #pragma unroll 4
        for (int kk = 0; kk < 32; kk++) {
            float a0 = czT[kk][tcg], a1 = czT[kk][tcg + 16];
            float bv[4];
            #pragma unroll
            for (int w = 0; w < 4; w++) bv[w] = colT[kk][tcol + 16 * w];
            #pragma unroll
            for (int w = 0; w < 4; w++) {
                sc[0][w] = fmaf(a0, bv[w], sc[0][w]);
                sc[1][w] = fmaf(a1, bv[w], sc[1][w]);
            }
        }
    }

    #pragma unroll
    for (int cc = 0; cc < 2; cc++) {
        int ci = tcg + 16 * cc;
        int rowid = cand[ci >> 1] + (ci & 1) * L;
        #pragma unroll
        for (int w = 0; w < 4; w++) {
            int gid = blk * 64 + tcol + 16 * w;
            if (gid == rowid) sc[cc][w] = -INFINITY;
        }
    }

    __syncthreads();
    #pragma unroll
    for (int cc = 0; cc < 2; cc++) {
        int ci = tcg + 16 * cc;
        float m = sc[cc][0];
        #pragma unroll
        for (int w = 1; w < 4; w++) m = fmaxf(m, sc[cc][w]);
        pr[tcol][ci] = m;
    }
    __syncthreads();
    if (tid < 32) {
        float m = pr[0][tid];
        #pragma unroll
        for (int x = 1; x < 16; x++) m = fmaxf(m, pr[x][tid]);
        Mrow[tid] = m;
    }
    __syncthreads();
    #pragma unroll
    for (int cc = 0; cc < 2; cc++) {
        int ci = tcg + 16 * cc;
        float Mf = Mrow[ci];
        float s = 0.f;
        #pragma unroll
        for (int w = 0; w < 4; w++) s += __expf(sc[cc][w] - Mf);
        pr[tcol][ci] = s;
    }
    __syncthreads();
    if (tid < 32) {
        float s = 0.f;
        #pragma unroll
        for (int x = 0; x < 16; x++) s += pr[x][tid];
        int gi = (b * 32 + tid) * NRSB + blk;
        g_cM[gi] = Mrow[tid];
        g_cS[gi] = s;
    }
}

// ----------------------------------------------------------------------------
// Kernel 6: final exact top-7 among candidates.
// ----------------------------------------------------------------------------
__global__ __launch_bounds__(32) void final_topk() {
    __shared__ float ls[B][32];
    __shared__ float val[NCAND];
    const int tid = threadIdx.x;
    for (int b = 0; b < B; b++) {
        float M = -INFINITY;
        #pragma unroll
        for (int blk = 0; blk < NRSB; blk++)
            M = fmaxf(M, g_cM[(b * 32 + tid) * NRSB + blk]);
        float S = 0.f;
        #pragma unroll
        for (int blk = 0; blk < NRSB; blk++)
            S += g_cS[(b * 32 + tid) * NRSB + blk] *
                 __expf(g_cM[(b * 32 + tid) * NRSB + blk] - M);
        ls[b][tid] = M + logf(S);
    }
    __syncwarp();
    if (tid < NCAND) {
        int t = g_cand[tid];
        float sum = 0.f;
        for (int b = 0; b < B; b++) {
            float tavg = 0.5f * (ls[b][2 * tid] + ls[b][2 * tid + 1]);
            sum += 0.5f * g_instAvg[b * L + t] + 0.5f * tavg - g_d[b * L + t];
        }
        val[tid] = sum * 0.25f;
    }
    __syncwarp();
    if (tid == 0) {
        unsigned used = 0;
        for (int k = 0; k < TOPK; k++) {
            float best = -INFINITY;
            int bc = -1, bt = 1 << 30;
            for (int c = 0; c < NCAND; c++) {
                if ((used >> c) & 1) continue;
                int t = g_cand[c];
                if (val[c] > best || (val[c] == best && t < bt)) {
                    best = val[c]; bc = c; bt = t;
                }
            }
            used |= 1u << bc;
            g_topk[k] = g_cand[bc];
        }
    }
}

// ----------------------------------------------------------------------------
// Kernel 7a: chunk sums for cumsum. Grid (32 chunks, H, B), 64 threads.
// ----------------------------------------------------------------------------
__global__ __launch_bounds__(64) void cumsum_pass1(const float* __restrict__ V) {
    const int chunk = blockIdx.x, h = blockIdx.y, b = blockIdx.z;
    const int e = threadIdx.x;
    const long baseIn = (long)b * L * C + (long)h * E + e;
    const int l0 = chunk * 64;
    float s = 0.f;
    #pragma unroll 8
    for (int i = 0; i < 64; i++) s += V[baseIn + (long)(l0 + i) * C];
    g_csum[((b * H + h) * 32 + chunk) * E + e] = s;
}

// ----------------------------------------------------------------------------
// Kernel 7b: PLAIN scan (no rescale) -> out, on the side stream.
// ----------------------------------------------------------------------------
__global__ __launch_bounds__(64) void cumsum_pass2_plain(const float* __restrict__ V,
                                                         float* __restrict__ out) {
    const int chunk = blockIdx.x, h = blockIdx.y, b = blockIdx.z;
    const int e = threadIdx.x;

    float off = 0.f;
    for (int c = 0; c < chunk; c++)
        off += g_csum[((b * H + h) * 32 + c) * E + e];

    const long baseIn = (long)b * L * C + (long)h * E + e;
    const long baseOut = ((long)(b * H + h) * L) * E + e;
    const int l0 = chunk * 64;
    float acc = off;
    #pragma unroll 4
    for (int i = 0; i < 64; i++) {
        const int l = l0 + i;
        acc += V[baseIn + (long)l * C];
        out[baseOut + (long)l * E] = acc;
    }
}

// ----------------------------------------------------------------------------
// Kernel 8: fixup — divide the TOPK selected rows by (idx+1).
// Grid (B*H), 448 threads = (7 k) x (64 e).  [grid-parallel: ~2us]
// ----------------------------------------------------------------------------
__global__ __launch_bounds__(448) void fixup_kernel(float* __restrict__ out) {
    const int bh = blockIdx.x;                 // 0..31
    const int k = threadIdx.x >> 6;            // 0..6
    const int e = threadIdx.x & 63;
    const int idx = g_topk[k];
    const size_t o = ((size_t)bh * L + idx) * E + e;
    out[o] = out[o] / (float)(idx + 1);
}

// ----------------------------------------------------------------------------
// Launch. temporal_mma stays the 4th kernel launch (ncu slot).
// ----------------------------------------------------------------------------
extern "C" void kernel_launch(void* const* d_in, const int* in_sizes, int n_in,
                              void* d_out, int out_size) {
    const float* Q = (const float*)d_in[0];
    const float* K = (const float*)d_in[1];
    const float* V = (const float*)d_in[2];
    float* out = (float*)d_out;

    static cudaStream_t s1 = nullptr;
    static cudaEvent_t evFork = nullptr, evJoin = nullptr;
    static bool inited = false;
    if (!inited) {
        cudaFuncSetAttribute(temporal_mma,
                             cudaFuncAttributeMaxDynamicSharedMemorySize, 65536);
        cudaStreamCreateWithFlags(&s1, cudaStreamNonBlocking);
        cudaEventCreateWithFlags(&evFork, cudaEventDisableTiming);
        cudaEventCreateWithFlags(&evJoin, cudaEventDisableTiming);
        inited = true;
    }

    cudaEventRecord(evFork, 0);
    cudaStreamWaitEvent(s1, evFork, 0);

    // side stream (launches 1-2)
    instance_kernel<<<L / 4, 128, 0, s1>>>(Q, K);
    cumsum_pass1<<<dim3(32, H, B), 64, 0, s1>>>(V);

    // main stream (launches 3-4)
    convert_kernel<<<(B * L2 * C) / 8 / 256, 256>>>(Q, K);
    temporal_mma<<<dim3(NPAIR, B), 256, 65536>>>();

    // side stream (launch 5) + join
    cumsum_pass2_plain<<<dim3(32, H, B), 64, 0, s1>>>(V, out);
    cudaEventRecord(evJoin, s1);
    cudaStreamWaitEvent(0, evJoin, 0);   // instAvg/d for combine; out for fixup

    // main tail (launches 6-9)
    combine_kernel<<<dim3(L / 64, B), 256>>>();
    cand_kernel<<<1, 256>>>();
    rescreen<<<dim3(NRSB, B), 256>>>(Q, K);
    final_topk<<<1, 32>>>();
    fixup_kernel<<<B * H, 448>>>(out);
}